// round 1
// baseline (speedup 1.0000x reference)
#include <cuda_runtime.h>

// Problem constants
#define NB 8
#define EDIM 256
#define HH 32
#define WW 32
#define NE 16384
#define M_TOK (NB * HH * WW)   // 8192 tokens

// GEMM tiling
#define BM 64
#define BN 128
#define BK 16
#define NTHR 128
#define BN_PAD 132   // +4 floats: breaks 16-way STS bank conflict, keeps 16B row alignment

__device__ float g_cnorm[NE];
__device__ int   g_idx[M_TOK];

// ---------------------------------------------------------------------------
// Kernel 1: codebook row norms  |c|^2
// 8 rows per 256-thread block, 32 lanes per row
// ---------------------------------------------------------------------------
__global__ void cnorm_kernel(const float* __restrict__ cb) {
    int row  = blockIdx.x * 8 + (threadIdx.x >> 5);
    int lane = threadIdx.x & 31;
    const float* r = cb + row * EDIM;
    float s = 0.f;
#pragma unroll
    for (int i = lane; i < EDIM; i += 32) {
        float v = r[i];
        s += v * v;
    }
#pragma unroll
    for (int o = 16; o > 0; o >>= 1) s += __shfl_down_sync(0xffffffffu, s, o);
    if (lane == 0) g_cnorm[row] = s;
}

// ---------------------------------------------------------------------------
// Kernel 2: fused distance-GEMM + per-token argmin
//   score[t][n] = |c_n|^2 - 2 * dot(x_t, c_n)      (|x|^2 irrelevant to argmin)
// CTA: 64 tokens x (loop over all 16384 codes in 128-wide tiles)
// 128 threads, 8x8 register micro-tile, BK=16 smem staging, register prefetch.
// ---------------------------------------------------------------------------
__global__ void __launch_bounds__(NTHR, 1)
vq_argmin_kernel(const float* __restrict__ z, const float* __restrict__ cb) {
    __shared__ float As[BK][BM];        // 4 KB   As[k][m]
    __shared__ float Bs[BK][BN_PAD];    // 8.25KB Bs[k][n]
    __shared__ float cns[BN];
    __shared__ float rv[BM][16];
    __shared__ int   ri[BM][16];

    const int tx = threadIdx.x;
    const int rt = tx >> 4;   // 0..7  : row-thread   (8 rows each)
    const int ct = tx & 15;   // 0..15 : col-thread   (8 cols each)

    const int t0 = blockIdx.x * BM;
    const int b  = t0 >> 10;          // 64 | 1024, so tile stays in one batch plane
    const int p0 = t0 & 1023;
    // x_t[e] = z[b, e, p]  ->  zb[e*1024 + m]
    const float* zb = z + (size_t)b * (EDIM * HH * WW) + p0;

    // A-load mapping: thread -> (m = tx&63, kk = tx>>6 stepping by 2)
    const int a_m   = tx & 63;
    const int a_kk0 = tx >> 6;              // 0..1
    // B-load mapping: thread -> (kk = tx&15, nsub = tx>>4, 16 n's stride 8)
    const int b_kk   = tx & 15;
    const int b_nsub = tx >> 4;             // 0..7

    float best_val[8];
    int   best_idx[8];
#pragma unroll
    for (int i = 0; i < 8; ++i) { best_val[i] = 3.4e38f; best_idx[i] = 0; }

    float a_pf[8];
    float b_pf[16];

    for (int n0 = 0; n0 < NE; n0 += BN) {
        __syncthreads();                      // protect cns/smem from prev readers
        cns[tx] = g_cnorm[n0 + tx];

        float acc[8][8];
#pragma unroll
        for (int i = 0; i < 8; ++i)
#pragma unroll
            for (int j = 0; j < 8; ++j) acc[i][j] = 0.f;

        // ---- preload k-tile 0 into registers ----
        {
            const int k0 = 0;
#pragma unroll
            for (int u = 0; u < 8; ++u) {
                int kk = a_kk0 + 2 * u;
                a_pf[u] = zb[(k0 + kk) * 1024 + a_m];
            }
#pragma unroll
            for (int j = 0; j < 16; ++j) {
                int n = b_nsub + j * 8;
                b_pf[j] = cb[(size_t)(n0 + n) * EDIM + k0 + b_kk];
            }
        }

#pragma unroll 1
        for (int kt = 0; kt < EDIM / BK; ++kt) {
            __syncthreads();
            // regs -> smem
#pragma unroll
            for (int u = 0; u < 8; ++u) As[a_kk0 + 2 * u][a_m] = a_pf[u];
#pragma unroll
            for (int j = 0; j < 16; ++j) Bs[b_kk][b_nsub + j * 8] = b_pf[j];
            __syncthreads();

            // prefetch next k-tile while computing
            if (kt + 1 < EDIM / BK) {
                const int k0 = (kt + 1) * BK;
#pragma unroll
                for (int u = 0; u < 8; ++u) {
                    int kk = a_kk0 + 2 * u;
                    a_pf[u] = zb[(k0 + kk) * 1024 + a_m];
                }
#pragma unroll
                for (int j = 0; j < 16; ++j) {
                    int n = b_nsub + j * 8;
                    b_pf[j] = cb[(size_t)(n0 + n) * EDIM + k0 + b_kk];
                }
            }

#pragma unroll
            for (int k = 0; k < BK; ++k) {
                float a[8], bb[8];
                float4 av0 = *(const float4*)&As[k][rt * 8];
                float4 av1 = *(const float4*)&As[k][rt * 8 + 4];
                float4 bv0 = *(const float4*)&Bs[k][ct * 8];
                float4 bv1 = *(const float4*)&Bs[k][ct * 8 + 4];
                a[0]=av0.x; a[1]=av0.y; a[2]=av0.z; a[3]=av0.w;
                a[4]=av1.x; a[5]=av1.y; a[6]=av1.z; a[7]=av1.w;
                bb[0]=bv0.x; bb[1]=bv0.y; bb[2]=bv0.z; bb[3]=bv0.w;
                bb[4]=bv1.x; bb[5]=bv1.y; bb[6]=bv1.z; bb[7]=bv1.w;
#pragma unroll
                for (int i = 0; i < 8; ++i)
#pragma unroll
                    for (int j = 0; j < 8; ++j)
                        acc[i][j] += a[i] * bb[j];
            }
        }

        // score + running argmin (n ascending within thread; strict < keeps first)
#pragma unroll
        for (int j = 0; j < 8; ++j) {
            int   n  = n0 + ct * 8 + j;
            float cn = cns[ct * 8 + j];
#pragma unroll
            for (int i = 0; i < 8; ++i) {
                float s = fmaf(-2.f, acc[i][j], cn);
                if (s < best_val[i]) { best_val[i] = s; best_idx[i] = n; }
            }
        }
    }

    // cross-thread reduction per token row (prefer smaller index on tie)
    __syncthreads();
#pragma unroll
    for (int i = 0; i < 8; ++i) {
        rv[rt * 8 + i][ct] = best_val[i];
        ri[rt * 8 + i][ct] = best_idx[i];
    }
    __syncthreads();
    if (tx < BM) {
        float bv = rv[tx][0];
        int   bi = ri[tx][0];
#pragma unroll
        for (int c = 1; c < 16; ++c) {
            float v  = rv[tx][c];
            int   id = ri[tx][c];
            if (v < bv || (v == bv && id < bi)) { bv = v; bi = id; }
        }
        g_idx[t0 + tx] = bi;
    }
}

// ---------------------------------------------------------------------------
// Kernel 3: gather  out[b,e,h,w] = codebook[idx[b,h,w], e]
// Block per (b,h); lanes map to w -> fully coalesced 128B writes.
// ---------------------------------------------------------------------------
__global__ void gather_kernel(const float* __restrict__ cb, float* __restrict__ out) {
    int bh = blockIdx.x;               // 0..255
    int b  = bh >> 5;
    int h  = bh & 31;
    int w  = threadIdx.x & 31;
    int e0 = threadIdx.x >> 5;         // 0..7

    int t   = b * 1024 + h * 32 + w;
    int idx = g_idx[t];
    const float* row = cb + (size_t)idx * EDIM;
    float* ob = out + (size_t)b * (EDIM * 1024) + h * 32 + w;

#pragma unroll
    for (int e = e0; e < EDIM; e += 8)
        ob[e * 1024] = row[e];
}

// ---------------------------------------------------------------------------
extern "C" void kernel_launch(void* const* d_in, const int* in_sizes, int n_in,
                              void* d_out, int out_size) {
    const float* z  = (const float*)d_in[0];   // [8,256,32,32]
    const float* cb = (const float*)d_in[1];   // [16384,256]
    float* out = (float*)d_out;                // [8,256,32,32]

    cnorm_kernel<<<NE / 8, 256>>>(cb);
    vq_argmin_kernel<<<M_TOK / BM, NTHR>>>(z, cb);
    gather_kernel<<<NB * HH, 256>>>(cb, out);
}